// round 5
// baseline (speedup 1.0000x reference)
#include <cuda_runtime.h>
#include <cuda_bf16.h>
#include <math.h>

#define MAXA 54
#define NB   1024
#define NN   (NB*MAXA)        /* 55296 nodes  */
#define DEG  16
#define NE   (NN*DEG)         /* 884736 edges */
#define HD   64
#define JJ   256
#define MMM  16

#define TILE_E 128
#define NTILES (NE/TILE_E)    /* 6912 */
#define NODES_PER_TILE (TILE_E/DEG) /* 8 */
#define STRIDE 72             /* padded activation row stride (bank-conflict free) */

typedef unsigned long long u64;

/* ------------- scratch: __device__ globals (allocation-free rule) ---------- */
__device__ float g_h1 [(size_t)NN*HD];
__device__ float g_P  [(size_t)NN*HD];
__device__ float g_Q  [(size_t)NN*HD];
__device__ float g_agg[(size_t)NN*HD];

/* ---------------------------- f32x2 helpers -------------------------------- */
__device__ __forceinline__ u64 pk(float lo, float hi) {
    u64 r; asm("mov.b64 %0,{%1,%2};" : "=l"(r) : "f"(lo), "f"(hi)); return r;
}
__device__ __forceinline__ void upk(u64 v, float &lo, float &hi) {
    asm("mov.b64 {%0,%1},%2;" : "=f"(lo), "=f"(hi) : "l"(v));
}
__device__ __forceinline__ void fma2(u64 &d, u64 a, u64 b) {
    asm("fma.rn.f32x2 %0,%1,%2,%0;" : "+l"(d) : "l"(a), "l"(b));
}
__device__ __forceinline__ float silu(float x) {
    return x / (1.f + __expf(-x));
}

/* Register-tiled GEMM: X is [128 rows x 64] in smem with row stride STRIDE,
   W is [K x 64] row-major in smem. Thread (ty,o0) accumulates rows
   ty*4..ty*4+3, cols o0..o0+7 into acc (4 rows x 4 f32x2). */
template<int K>
__device__ __forceinline__ void gemm_acc(const float* __restrict__ X,
                                         const float* __restrict__ W,
                                         int ty, int o0, u64 acc[4][4]) {
#pragma unroll 4
    for (int k = 0; k < K; ++k) {
        float4 wa = *(const float4*)(W + k*64 + o0);
        float4 wb = *(const float4*)(W + k*64 + o0 + 4);
        u64 w0 = pk(wa.x, wa.y), w1 = pk(wa.z, wa.w);
        u64 w2 = pk(wb.x, wb.y), w3 = pk(wb.z, wb.w);
#pragma unroll
        for (int i = 0; i < 4; ++i) {
            float x = X[(ty*4 + i)*STRIDE + k];
            u64 xp = pk(x, x);
            fma2(acc[i][0], xp, w0);
            fma2(acc[i][1], xp, w1);
            fma2(acc[i][2], xp, w2);
            fma2(acc[i][3], xp, w3);
        }
    }
}

/* =========================== Kernel A: node prep =========================== */
/* block = 128 nodes, 256 threads.
   h1 = h + node_embed gather  -> g_h1 (and smem)
   g_P = h1 @ mes_w1[0:64], g_Q = h1 @ mes_w1[64:128]
   g_agg zeroed. */
#define A_W1A 0
#define A_W1B 4096
#define A_SH1 8192
#define A_SMEM_FLOATS (8192 + 128*STRIDE)

__global__ void __launch_bounds__(256, 1)
kernel_prep(const float* __restrict__ h,
            const float* __restrict__ node_embed,
            const float* __restrict__ mes_w1,
            const int*   __restrict__ node_holder,
            const int*   __restrict__ jt_idx)
{
    extern __shared__ float s[];
    const int tid = threadIdx.x;
    const int nb  = blockIdx.x * 128;

    for (int idx = tid; idx < 4096; idx += 256) {
        s[A_W1A + idx] = mes_w1[idx];
        s[A_W1B + idx] = mes_w1[4096 + idx];
    }
    /* stage h1, write g_h1, zero g_agg */
    for (int idx = tid; idx < 128*64; idx += 256) {
        int l = idx >> 6, o = idx & 63;
        int node = nb + l;
        int cand = node / MAXA;
        int jn   = node_holder[node];
        int j    = jt_idx[cand];
        int jn1  = jn > 0 ? jn - 1 : 0;
        float v  = h[(size_t)node*64 + o] + node_embed[((size_t)j*MMM + jn1)*64 + o];
        s[A_SH1 + l*STRIDE + o] = v;
        g_h1[(size_t)node*64 + o] = v;
        g_agg[(size_t)node*64 + o] = 0.f;
    }
    __syncthreads();

    const int tx = tid & 7, ty = tid >> 3;
    const int o0 = tx * 8;

    u64 acc[4][4];
#pragma unroll
    for (int i = 0; i < 4; ++i)
#pragma unroll
        for (int p = 0; p < 4; ++p) acc[i][p] = 0ull;
    gemm_acc<64>(s + A_SH1, s + A_W1A, ty, o0, acc);
#pragma unroll
    for (int i = 0; i < 4; ++i) {
        size_t base = (size_t)(nb + ty*4 + i) * 64 + o0;
        float v[8];
#pragma unroll
        for (int p = 0; p < 4; ++p) upk(acc[i][p], v[2*p], v[2*p+1]);
        *(float4*)(g_P + base)     = make_float4(v[0], v[1], v[2], v[3]);
        *(float4*)(g_P + base + 4) = make_float4(v[4], v[5], v[6], v[7]);
    }
#pragma unroll
    for (int i = 0; i < 4; ++i)
#pragma unroll
        for (int p = 0; p < 4; ++p) acc[i][p] = 0ull;
    gemm_acc<64>(s + A_SH1, s + A_W1B, ty, o0, acc);
#pragma unroll
    for (int i = 0; i < 4; ++i) {
        size_t base = (size_t)(nb + ty*4 + i) * 64 + o0;
        float v[8];
#pragma unroll
        for (int p = 0; p < 4; ++p) upk(acc[i][p], v[2*p], v[2*p+1]);
        *(float4*)(g_Q + base)     = make_float4(v[0], v[1], v[2], v[3]);
        *(float4*)(g_Q + base + 4) = make_float4(v[4], v[5], v[6], v[7]);
    }
}

/* =========================== Kernel B: edges =============================== */
/* persistent blocks, 128 edges (= 8 full nodes) per tile, 256 threads */
#define OFF_W1E  0
#define OFF_W2   4096
#define OFF_CW1  8192
#define OFF_EW1  12288          /* 129*64 = 8256 */
#define OFF_EW2  20544
#define OFF_W1R  24640
#define OFF_B1   24704
#define OFF_B2   24768
#define OFF_CB1  24832
#define OFF_CW2  24896
#define OFF_EB1  24960
#define OFF_EB2  25024
#define OFF_BUFE 25088          /* 128*72 = 9216 */
#define OFF_BUFT 34304
#define OFF_BUFF 43520
#define OFF_SCOL 52736          /* int x128 */
#define OFF_SMB  52864          /* int x128 */
#define OFF_SEM  52992
#define OFF_SRAD 53120
#define OFF_SCD  53248          /* 128*3 */
#define OFF_SGT  53632
#define OFF_STR  53760          /* 128*3 */
#define B_SMEM_FLOATS 54144

__global__ void __launch_bounds__(256, 1)
kernel_edges(const float* __restrict__ coord,
             const float* __restrict__ edge_attr,
             const float* __restrict__ jt_mess,
             const float* __restrict__ node_mask,
             const float* __restrict__ edge_mask,
             const float* __restrict__ mes_w1,
             const float* __restrict__ mes_b1,
             const float* __restrict__ mes_w2,
             const float* __restrict__ mes_b2,
             const float* __restrict__ edge_w1,
             const float* __restrict__ edge_b1,
             const float* __restrict__ edge_w2,
             const float* __restrict__ edge_b2,
             const float* __restrict__ coord_w1,
             const float* __restrict__ coord_b1,
             const float* __restrict__ coord_w2,
             const int*   __restrict__ colidx,     /* edge_index + NE */
             const int*   __restrict__ mess_holder,
             const int*   __restrict__ jt_idx,
             float* __restrict__ outC,
             float* __restrict__ outE)
{
    extern __shared__ float s[];
    int* scol = (int*)(s + OFF_SCOL);
    int* smb  = (int*)(s + OFF_SMB);
    const int tid = threadIdx.x;
    const int tx = tid & 7, ty = tid >> 3;
    const int o0 = tx * 8;

    /* ---- load all weights once (persistent block) ---- */
    for (int idx = tid; idx < 4096; idx += 256) {
        s[OFF_W1E + idx] = mes_w1[129*64 + idx];
        s[OFF_W2  + idx] = mes_w2[idx];
        s[OFF_CW1 + idx] = coord_w1[idx];
        s[OFF_EW2 + idx] = edge_w2[idx];
    }
    for (int idx = tid; idx < 8256; idx += 256) s[OFF_EW1 + idx] = edge_w1[idx];
    if (tid < 64) {
        s[OFF_W1R + tid] = mes_w1[128*64 + tid];
        s[OFF_B1  + tid] = mes_b1[tid];
        s[OFF_B2  + tid] = mes_b2[tid];
        s[OFF_CB1 + tid] = coord_b1[tid];
        s[OFF_CW2 + tid] = coord_w2[tid];
        s[OFF_EB1 + tid] = edge_b1[tid];
        s[OFF_EB2 + tid] = edge_b2[tid];
    }
    __syncthreads();

    for (int tile = blockIdx.x; tile < NTILES; tile += gridDim.x) {
        const int e0 = tile * TILE_E;

        /* ---- per-edge metadata ---- */
        if (tid < 128) {
            int eg = e0 + tid;
            int c  = colidx[eg];
            scol[tid] = c;
            int r = eg >> 4;
            int cand = r / MAXA;
            int am = r - cand*MAXA, ac = c - cand*MAXA;
            const int* jp = mess_holder + ((((size_t)cand*MAXA + am)*MAXA + ac) << 1);
            int jr = jp[0], jc = jp[1];
            int mb = -1;
            if (jr != 0 && jc != 0) {
                int jr1 = jr > 0 ? jr - 1 : 0;
                int jc1 = jc > 0 ? jc - 1 : 0;
                mb = ((jt_idx[cand]*MMM + jr1)*MMM + jc1) * 64;
            }
            smb[tid] = mb;
            s[OFF_SEM + tid] = edge_mask[eg];
            float dx = coord[r*3+0] - coord[c*3+0];
            float dy = coord[r*3+1] - coord[c*3+1];
            float dz = coord[r*3+2] - coord[c*3+2];
            float rad = dx*dx + dy*dy + dz*dz;
            s[OFF_SRAD + tid] = rad;
            float inv = 1.f / (sqrtf(rad + 1e-8f) + 1.f);
            s[OFF_SCD + tid*3 + 0] = dx * inv;
            s[OFF_SCD + tid*3 + 1] = dy * inv;
            s[OFF_SCD + tid*3 + 2] = dz * inv;
        }
        __syncthreads();

        /* ---- stage edge_attr1 = edge_attr + mess ---- */
        for (int idx = tid; idx < 128*16; idx += 256) {
            int e = idx >> 4, o4 = (idx & 15) << 2;
            int eg = e0 + e;
            int mb = smb[e];
            float4 v = *(const float4*)(edge_attr + (size_t)eg*64 + o4);
            if (mb >= 0) {
                float4 m = *(const float4*)(jt_mess + (size_t)mb + o4);
                v.x += m.x; v.y += m.y; v.z += m.z; v.w += m.w;
            }
            *(float4*)(s + OFF_BUFE + e*STRIDE + o4) = v;
        }
        __syncthreads();

        u64 acc[4][4];

        /* ---- mes GEMM1: P[row]+Q[col]+rad*w1r+b1 + bufE @ w1e ; silu -> bufT */
        {
            int rn = (e0 + ty*4) >> 4;
            float4 pA = *(const float4*)(g_P + (size_t)rn*64 + o0);
            float4 pB = *(const float4*)(g_P + (size_t)rn*64 + o0 + 4);
            float bb[8], ww[8];
#pragma unroll
            for (int j = 0; j < 8; ++j) { bb[j] = s[OFF_B1+o0+j]; ww[j] = s[OFF_W1R+o0+j]; }
            float pv[8] = {pA.x,pA.y,pA.z,pA.w,pB.x,pB.y,pB.z,pB.w};
#pragma unroll
            for (int i = 0; i < 4; ++i) {
                int e = ty*4 + i;
                int c = scol[e];
                float rad = s[OFF_SRAD + e];
                float4 qA = *(const float4*)(g_Q + (size_t)c*64 + o0);
                float4 qB = *(const float4*)(g_Q + (size_t)c*64 + o0 + 4);
                float qv[8] = {qA.x,qA.y,qA.z,qA.w,qB.x,qB.y,qB.z,qB.w};
                float v[8];
#pragma unroll
                for (int j = 0; j < 8; ++j) v[j] = bb[j] + rad*ww[j] + pv[j] + qv[j];
#pragma unroll
                for (int p = 0; p < 4; ++p) acc[i][p] = pk(v[2*p], v[2*p+1]);
            }
        }
        gemm_acc<64>(s + OFF_BUFE, s + OFF_W1E, ty, o0, acc);
#pragma unroll
        for (int i = 0; i < 4; ++i) {
            float* d = s + OFF_BUFT + (ty*4+i)*STRIDE + o0;
#pragma unroll
            for (int p = 0; p < 4; ++p) {
                float a, b; upk(acc[i][p], a, b);
                d[2*p] = silu(a); d[2*p+1] = silu(b);
            }
        }
        __syncthreads();

        /* ---- mes GEMM2: silu(bufT @ w2 + b2) * emask -> bufF, + global agg red */
#pragma unroll
        for (int i = 0; i < 4; ++i)
#pragma unroll
            for (int p = 0; p < 4; ++p)
                acc[i][p] = pk(s[OFF_B2+o0+2*p], s[OFF_B2+o0+2*p+1]);
        gemm_acc<64>(s + OFF_BUFT, s + OFF_W2, ty, o0, acc);
#pragma unroll
        for (int i = 0; i < 4; ++i) {
            int e = ty*4 + i;
            float em = s[OFF_SEM + e];
            int c = scol[e];
            float* d = s + OFF_BUFF + e*STRIDE + o0;
            float* ga = g_agg + (size_t)c*64 + o0;
#pragma unroll
            for (int p = 0; p < 4; ++p) {
                float a, b; upk(acc[i][p], a, b);
                a = silu(a) * em; b = silu(b) * em;
                d[2*p] = a; d[2*p+1] = b;
                atomicAdd(ga + 2*p, a);
                atomicAdd(ga + 2*p + 1, b);
            }
        }
        __syncthreads();

        /* ---- coord gate: silu(bufF @ cw1 + cb1) . cw2 -> sgate ---- */
#pragma unroll
        for (int i = 0; i < 4; ++i)
#pragma unroll
            for (int p = 0; p < 4; ++p)
                acc[i][p] = pk(s[OFF_CB1+o0+2*p], s[OFF_CB1+o0+2*p+1]);
        gemm_acc<64>(s + OFF_BUFF, s + OFF_CW1, ty, o0, acc);
        {
            float cw[8];
#pragma unroll
            for (int j = 0; j < 8; ++j) cw[j] = s[OFF_CW2+o0+j];
#pragma unroll
            for (int i = 0; i < 4; ++i) {
                float pd = 0.f;
#pragma unroll
                for (int p = 0; p < 4; ++p) {
                    float a, b; upk(acc[i][p], a, b);
                    pd += silu(a)*cw[2*p] + silu(b)*cw[2*p+1];
                }
                pd += __shfl_xor_sync(0xffffffffu, pd, 1);
                pd += __shfl_xor_sync(0xffffffffu, pd, 2);
                pd += __shfl_xor_sync(0xffffffffu, pd, 4);
                if (tx == 0) s[OFF_SGT + ty*4 + i] = pd;
            }
        }
        __syncthreads();

        if (tid < 128) {
            float g = s[OFF_SGT + tid] * s[OFF_SEM + tid];
            s[OFF_STR + tid*3 + 0] = s[OFF_SCD + tid*3 + 0] * g;
            s[OFF_STR + tid*3 + 1] = s[OFF_SCD + tid*3 + 1] * g;
            s[OFF_STR + tid*3 + 2] = s[OFF_SCD + tid*3 + 2] * g;
        }
        __syncthreads();

        if (tid < NODES_PER_TILE*3) {
            int n = tid / 3, c = tid - n*3;
            float sum = 0.f;
#pragma unroll
            for (int k = 0; k < DEG; ++k) sum += s[OFF_STR + (n*DEG + k)*3 + c];
            int gn = tile*NODES_PER_TILE + n;
            outC[gn*3 + c] = (coord[gn*3 + c] + sum) * node_mask[gn];
        }

        /* ---- edge MLP: silu([bufF, rad, bufE] @ ew1 + eb1) -> bufT ---- */
        {
            float bb[8], ww[8];
#pragma unroll
            for (int j = 0; j < 8; ++j) { bb[j] = s[OFF_EB1+o0+j]; ww[j] = s[OFF_EW1 + 64*64 + o0 + j]; }
#pragma unroll
            for (int i = 0; i < 4; ++i) {
                float rad = s[OFF_SRAD + ty*4 + i];
#pragma unroll
                for (int p = 0; p < 4; ++p)
                    acc[i][p] = pk(bb[2*p] + rad*ww[2*p], bb[2*p+1] + rad*ww[2*p+1]);
            }
        }
        gemm_acc<64>(s + OFF_BUFF, s + OFF_EW1,           ty, o0, acc);
        gemm_acc<64>(s + OFF_BUFE, s + OFF_EW1 + 65*64,   ty, o0, acc);
#pragma unroll
        for (int i = 0; i < 4; ++i) {
            float* d = s + OFF_BUFT + (ty*4+i)*STRIDE + o0;
#pragma unroll
            for (int p = 0; p < 4; ++p) {
                float a, b; upk(acc[i][p], a, b);
                d[2*p] = silu(a); d[2*p+1] = silu(b);
            }
        }
        __syncthreads();

        /* ---- edge GEMM2: (bufT @ ew2 + eb2) * emask -> outE ---- */
#pragma unroll
        for (int i = 0; i < 4; ++i)
#pragma unroll
            for (int p = 0; p < 4; ++p)
                acc[i][p] = pk(s[OFF_EB2+o0+2*p], s[OFF_EB2+o0+2*p+1]);
        gemm_acc<64>(s + OFF_BUFT, s + OFF_EW2, ty, o0, acc);
#pragma unroll
        for (int i = 0; i < 4; ++i) {
            int e = ty*4 + i;
            float em = s[OFF_SEM + e];
            size_t eg = (size_t)(e0 + e);
            float v[8];
#pragma unroll
            for (int p = 0; p < 4; ++p) {
                float a, b; upk(acc[i][p], a, b);
                v[2*p] = a*em; v[2*p+1] = b*em;
            }
            *(float4*)(outE + eg*64 + o0)     = make_float4(v[0], v[1], v[2], v[3]);
            *(float4*)(outE + eg*64 + o0 + 4) = make_float4(v[4], v[5], v[6], v[7]);
        }
        __syncthreads();  /* buffers reused next tile */
    }
}

/* =========================== Kernel C: node MLP ============================ */
#define C_NW1  0
#define C_NW2  8192
#define C_NB1  12288
#define C_NB2  12352
#define C_BA   12416
#define C_BB   (12416 + 128*STRIDE)
#define C_BT   (12416 + 2*128*STRIDE)
#define C_SMEM_FLOATS (12416 + 3*128*STRIDE)

__global__ void __launch_bounds__(256, 1)
kernel_nodes(const float* __restrict__ node_w1,
             const float* __restrict__ node_b1,
             const float* __restrict__ node_w2,
             const float* __restrict__ node_b2,
             const float* __restrict__ node_mask,
             float* __restrict__ outH)
{
    extern __shared__ float s[];
    const int tid = threadIdx.x;
    const int nb  = blockIdx.x * 128;
    const int tx = tid & 7, ty = tid >> 3;
    const int o0 = tx * 8;

    for (int idx = tid; idx < 8192; idx += 256) s[C_NW1 + idx] = node_w1[idx];
    for (int idx = tid; idx < 4096; idx += 256) s[C_NW2 + idx] = node_w2[idx];
    if (tid < 64) { s[C_NB1 + tid] = node_b1[tid]; s[C_NB2 + tid] = node_b2[tid]; }
    for (int idx = tid; idx < 128*16; idx += 256) {
        int l = idx >> 4, o4 = (idx & 15) << 2;
        size_t base = (size_t)(nb + l)*64 + o4;
        *(float4*)(s + C_BA + l*STRIDE + o4) = *(const float4*)(g_h1 + base);
        *(float4*)(s + C_BB + l*STRIDE + o4) = *(const float4*)(g_agg + base);
    }
    __syncthreads();

    u64 acc[4][4];
#pragma unroll
    for (int i = 0; i < 4; ++i)
#pragma unroll
        for (int p = 0; p < 4; ++p)
            acc[i][p] = pk(s[C_NB1+o0+2*p], s[C_NB1+o0+2*p+1]);
    gemm_acc<64>(s + C_BA, s + C_NW1,         ty, o0, acc);
    gemm_acc<64>(s + C_BB, s + C_NW1 + 64*64, ty, o0, acc);
#pragma unroll
    for (int i = 0; i < 4; ++i) {
        float* d = s + C_BT + (ty*4+i)*STRIDE + o0;
#pragma unroll
        for (int p = 0; p < 4; ++p) {
            float a, b; upk(acc[i][p], a, b);
            d[2*p] = silu(a); d[2*p+1] = silu(b);
        }
    }
    __syncthreads();

#pragma unroll
    for (int i = 0; i < 4; ++i)
#pragma unroll
        for (int p = 0; p < 4; ++p)
            acc[i][p] = pk(s[C_NB2+o0+2*p], s[C_NB2+o0+2*p+1]);
    gemm_acc<64>(s + C_BT, s + C_NW2, ty, o0, acc);
#pragma unroll
    for (int i = 0; i < 4; ++i) {
        int l = ty*4 + i;
        int node = nb + l;
        float nm = node_mask[node];
        const float* h1p = s + C_BA + l*STRIDE + o0;
        float v[8];
#pragma unroll
        for (int p = 0; p < 4; ++p) {
            float a, b; upk(acc[i][p], a, b);
            v[2*p]   = (h1p[2*p]   + a) * nm;
            v[2*p+1] = (h1p[2*p+1] + b) * nm;
        }
        size_t base = (size_t)node*64 + o0;
        *(float4*)(outH + base)     = make_float4(v[0], v[1], v[2], v[3]);
        *(float4*)(outH + base + 4) = make_float4(v[4], v[5], v[6], v[7]);
    }
}

/* =============================== launcher ================================== */
extern "C" void kernel_launch(void* const* d_in, const int* in_sizes, int n_in,
                              void* d_out, int out_size)
{
    const float* h          = (const float*)d_in[0];
    const float* coord      = (const float*)d_in[1];
    const float* edge_attr  = (const float*)d_in[2];
    const float* jt_mess    = (const float*)d_in[3];
    const float* node_embed = (const float*)d_in[4];
    const float* node_mask  = (const float*)d_in[5];
    const float* edge_mask  = (const float*)d_in[6];
    const float* mes_w1     = (const float*)d_in[7];
    const float* mes_b1     = (const float*)d_in[8];
    const float* mes_w2     = (const float*)d_in[9];
    const float* mes_b2     = (const float*)d_in[10];
    const float* edge_w1    = (const float*)d_in[11];
    const float* edge_b1    = (const float*)d_in[12];
    const float* edge_w2    = (const float*)d_in[13];
    const float* edge_b2    = (const float*)d_in[14];
    const float* node_w1    = (const float*)d_in[15];
    const float* node_b1    = (const float*)d_in[16];
    const float* node_w2    = (const float*)d_in[17];
    const float* node_b2    = (const float*)d_in[18];
    const float* coord_w1   = (const float*)d_in[19];
    const float* coord_b1   = (const float*)d_in[20];
    const float* coord_w2   = (const float*)d_in[21];
    const int*   edge_index = (const int*)d_in[22];
    const int*   mess_holder= (const int*)d_in[23];
    const int*   node_holder= (const int*)d_in[24];
    const int*   jt_idx     = (const int*)d_in[25];

    float* outH = (float*)d_out;
    float* outC = outH + (size_t)NN*HD;
    float* outE = outC + (size_t)NN*3;

    const int   smemA = A_SMEM_FLOATS * 4;
    const int   smemB = B_SMEM_FLOATS * 4;
    const int   smemC = C_SMEM_FLOATS * 4;

    cudaFuncSetAttribute(kernel_prep,  cudaFuncAttributeMaxDynamicSharedMemorySize, smemA);
    cudaFuncSetAttribute(kernel_edges, cudaFuncAttributeMaxDynamicSharedMemorySize, smemB);
    cudaFuncSetAttribute(kernel_nodes, cudaFuncAttributeMaxDynamicSharedMemorySize, smemC);

    kernel_prep<<<NN/128, 256, smemA>>>(h, node_embed, mes_w1, node_holder, jt_idx);

    kernel_edges<<<296, 256, smemB>>>(coord, edge_attr, jt_mess, node_mask, edge_mask,
                                      mes_w1, mes_b1, mes_w2, mes_b2,
                                      edge_w1, edge_b1, edge_w2, edge_b2,
                                      coord_w1, coord_b1, coord_w2,
                                      edge_index + NE, mess_holder, jt_idx,
                                      outC, outE);

    kernel_nodes<<<NN/128, 256, smemC>>>(node_w1, node_b1, node_w2, node_b2,
                                         node_mask, outH);
}

// round 6
// speedup vs baseline: 1.4576x; 1.4576x over previous
#include <cuda_runtime.h>
#include <cuda_bf16.h>
#include <math.h>

#define MAXA 54
#define NB   1024
#define NN   (NB*MAXA)        /* 55296 nodes  */
#define DEG  16
#define NE   (NN*DEG)         /* 884736 edges */
#define HD   64
#define JJ   256
#define MMM  16

#define TILE_E 128
#define NTILES (NE/TILE_E)    /* 6912 */
#define NODES_PER_TILE (TILE_E/DEG) /* 8 */
#define STRIDE 68             /* padded activation row stride: 4*STRIDE ≡ 16 mod 32 banks */

typedef unsigned long long u64;

/* ------------- scratch: __device__ globals (allocation-free rule) ---------- */
__device__ float g_h1 [(size_t)NN*HD];
__device__ float g_P  [(size_t)NN*HD];
__device__ float g_Q  [(size_t)NN*HD];
__device__ float g_agg[(size_t)NN*HD];

/* ---------------------------- f32x2 helpers -------------------------------- */
__device__ __forceinline__ u64 pk(float lo, float hi) {
    u64 r; asm("mov.b64 %0,{%1,%2};" : "=l"(r) : "f"(lo), "f"(hi)); return r;
}
__device__ __forceinline__ void upk(u64 v, float &lo, float &hi) {
    asm("mov.b64 {%0,%1},%2;" : "=f"(lo), "=f"(hi) : "l"(v));
}
__device__ __forceinline__ void fma2(u64 &d, u64 a, u64 b) {
    asm("fma.rn.f32x2 %0,%1,%2,%0;" : "+l"(d) : "l"(a), "l"(b));
}
__device__ __forceinline__ float silu(float x) {
    return x / (1.f + __expf(-x));
}
__device__ __forceinline__ void red4(float* p, float a, float b, float c, float d) {
    asm volatile("red.global.add.v4.f32 [%0], {%1,%2,%3,%4};"
                 :: "l"(p), "f"(a), "f"(b), "f"(c), "f"(d) : "memory");
}

/* Register-tiled GEMM.
   X: [128 rows x K] in smem, row stride STRIDE floats.
   W: [K x 64] row-major in smem.
   Thread (ty, tx): rows ty*4..ty*4+3; cols c0..c0+3 (acc[i][0..1]) and
   c0+32..c0+35 (acc[i][2..3]) where c0 = tx*4.
   X loaded as float4 along k (one LDS.128 per row per 4 k) — warp addresses
   at stride 1088B are only 2-way bank conflicted with STRIDE=68.
   W loads are 128B-contiguous across the 8 tx threads -> conflict-free. */
template<int K>
__device__ __forceinline__ void gemm_acc(const float* __restrict__ X,
                                         const float* __restrict__ W,
                                         int ty, int c0, u64 acc[4][4]) {
#pragma unroll 2
    for (int k4 = 0; k4 < K/4; ++k4) {
        float4 xv[4];
#pragma unroll
        for (int i = 0; i < 4; ++i)
            xv[i] = *(const float4*)(X + (ty*4 + i)*STRIDE + k4*4);
#pragma unroll
        for (int kk = 0; kk < 4; ++kk) {
            const float* Wk = W + (k4*4 + kk)*64;
            float4 wa = *(const float4*)(Wk + c0);
            float4 wb = *(const float4*)(Wk + c0 + 32);
            u64 w0 = pk(wa.x, wa.y), w1 = pk(wa.z, wa.w);
            u64 w2 = pk(wb.x, wb.y), w3 = pk(wb.z, wb.w);
#pragma unroll
            for (int i = 0; i < 4; ++i) {
                float x = (kk == 0) ? xv[i].x : (kk == 1) ? xv[i].y
                        : (kk == 2) ? xv[i].z : xv[i].w;
                u64 xp = pk(x, x);
                fma2(acc[i][0], xp, w0);
                fma2(acc[i][1], xp, w1);
                fma2(acc[i][2], xp, w2);
                fma2(acc[i][3], xp, w3);
            }
        }
    }
}

/* =========================== Kernel A: node prep =========================== */
#define A_W1A 0
#define A_W1B 4096
#define A_SH1 8192
#define A_SMEM_FLOATS (8192 + 128*STRIDE)

__global__ void __launch_bounds__(256, 1)
kernel_prep(const float* __restrict__ h,
            const float* __restrict__ node_embed,
            const float* __restrict__ mes_w1,
            const int*   __restrict__ node_holder,
            const int*   __restrict__ jt_idx)
{
    extern __shared__ float s[];
    const int tid = threadIdx.x;
    const int nb  = blockIdx.x * 128;

    for (int idx = tid; idx < 4096; idx += 256) {
        s[A_W1A + idx] = mes_w1[idx];
        s[A_W1B + idx] = mes_w1[4096 + idx];
    }
    for (int idx = tid; idx < 128*64; idx += 256) {
        int l = idx >> 6, o = idx & 63;
        int node = nb + l;
        int cand = node / MAXA;
        int jn   = node_holder[node];
        int j    = jt_idx[cand];
        int jn1  = jn > 0 ? jn - 1 : 0;
        float v  = h[(size_t)node*64 + o] + node_embed[((size_t)j*MMM + jn1)*64 + o];
        s[A_SH1 + l*STRIDE + o] = v;
        g_h1[(size_t)node*64 + o] = v;
        g_agg[(size_t)node*64 + o] = 0.f;
    }
    __syncthreads();

    const int tx = tid & 7, ty = tid >> 3;
    const int c0 = tx * 4;

    u64 acc[4][4];
#pragma unroll
    for (int i = 0; i < 4; ++i)
#pragma unroll
        for (int p = 0; p < 4; ++p) acc[i][p] = 0ull;
    gemm_acc<64>(s + A_SH1, s + A_W1A, ty, c0, acc);
#pragma unroll
    for (int i = 0; i < 4; ++i) {
        size_t base = (size_t)(nb + ty*4 + i) * 64;
        float v[8];
#pragma unroll
        for (int p = 0; p < 4; ++p) upk(acc[i][p], v[2*p], v[2*p+1]);
        *(float4*)(g_P + base + c0)      = make_float4(v[0], v[1], v[2], v[3]);
        *(float4*)(g_P + base + c0 + 32) = make_float4(v[4], v[5], v[6], v[7]);
    }
#pragma unroll
    for (int i = 0; i < 4; ++i)
#pragma unroll
        for (int p = 0; p < 4; ++p) acc[i][p] = 0ull;
    gemm_acc<64>(s + A_SH1, s + A_W1B, ty, c0, acc);
#pragma unroll
    for (int i = 0; i < 4; ++i) {
        size_t base = (size_t)(nb + ty*4 + i) * 64;
        float v[8];
#pragma unroll
        for (int p = 0; p < 4; ++p) upk(acc[i][p], v[2*p], v[2*p+1]);
        *(float4*)(g_Q + base + c0)      = make_float4(v[0], v[1], v[2], v[3]);
        *(float4*)(g_Q + base + c0 + 32) = make_float4(v[4], v[5], v[6], v[7]);
    }
}

/* =========================== Kernel B: edges =============================== */
#define OFF_W1E  0
#define OFF_W2   4096
#define OFF_CW1  8192
#define OFF_EW1  12288          /* 129*64 = 8256 */
#define OFF_EW2  20544
#define OFF_W1R  24640
#define OFF_B1   24704
#define OFF_B2   24768
#define OFF_CB1  24832
#define OFF_CW2  24896
#define OFF_EB1  24960
#define OFF_EB2  25024
#define OFF_BUFE 25088          /* 128*68 = 8704 */
#define OFF_BUFT 33792
#define OFF_BUFF 42496
#define OFF_SCOL 51200          /* int x128 */
#define OFF_SMB  51328          /* int x128 */
#define OFF_SEM  51456
#define OFF_SRAD 51584
#define OFF_SCD  51712          /* 128*3 */
#define OFF_SGT  52096
#define OFF_STR  52224          /* 128*3 */
#define B_SMEM_FLOATS 52608

__global__ void __launch_bounds__(256, 1)
kernel_edges(const float* __restrict__ coord,
             const float* __restrict__ edge_attr,
             const float* __restrict__ jt_mess,
             const float* __restrict__ node_mask,
             const float* __restrict__ edge_mask,
             const float* __restrict__ mes_w1,
             const float* __restrict__ mes_b1,
             const float* __restrict__ mes_w2,
             const float* __restrict__ mes_b2,
             const float* __restrict__ edge_w1,
             const float* __restrict__ edge_b1,
             const float* __restrict__ edge_w2,
             const float* __restrict__ edge_b2,
             const float* __restrict__ coord_w1,
             const float* __restrict__ coord_b1,
             const float* __restrict__ coord_w2,
             const int*   __restrict__ colidx,     /* edge_index + NE */
             const int*   __restrict__ mess_holder,
             const int*   __restrict__ jt_idx,
             float* __restrict__ outC,
             float* __restrict__ outE)
{
    extern __shared__ float s[];
    int* scol = (int*)(s + OFF_SCOL);
    int* smb  = (int*)(s + OFF_SMB);
    const int tid = threadIdx.x;
    const int tx = tid & 7, ty = tid >> 3;
    const int c0 = tx * 4;

    /* ---- load all weights once (persistent block) ---- */
    for (int idx = tid; idx < 4096; idx += 256) {
        s[OFF_W1E + idx] = mes_w1[129*64 + idx];
        s[OFF_W2  + idx] = mes_w2[idx];
        s[OFF_CW1 + idx] = coord_w1[idx];
        s[OFF_EW2 + idx] = edge_w2[idx];
    }
    for (int idx = tid; idx < 8256; idx += 256) s[OFF_EW1 + idx] = edge_w1[idx];
    if (tid < 64) {
        s[OFF_W1R + tid] = mes_w1[128*64 + tid];
        s[OFF_B1  + tid] = mes_b1[tid];
        s[OFF_B2  + tid] = mes_b2[tid];
        s[OFF_CB1 + tid] = coord_b1[tid];
        s[OFF_CW2 + tid] = coord_w2[tid];
        s[OFF_EB1 + tid] = edge_b1[tid];
        s[OFF_EB2 + tid] = edge_b2[tid];
    }
    __syncthreads();

    for (int tile = blockIdx.x; tile < NTILES; tile += gridDim.x) {
        const int e0 = tile * TILE_E;

        /* ---- per-edge metadata ---- */
        if (tid < 128) {
            int eg = e0 + tid;
            int c  = colidx[eg];
            scol[tid] = c;
            int r = eg >> 4;
            int cand = r / MAXA;
            int am = r - cand*MAXA, ac = c - cand*MAXA;
            const int* jp = mess_holder + ((((size_t)cand*MAXA + am)*MAXA + ac) << 1);
            int jr = jp[0], jc = jp[1];
            int mb = -1;
            if (jr != 0 && jc != 0) {
                int jr1 = jr > 0 ? jr - 1 : 0;
                int jc1 = jc > 0 ? jc - 1 : 0;
                mb = ((jt_idx[cand]*MMM + jr1)*MMM + jc1) * 64;
            }
            smb[tid] = mb;
            s[OFF_SEM + tid] = edge_mask[eg];
            float dx = coord[r*3+0] - coord[c*3+0];
            float dy = coord[r*3+1] - coord[c*3+1];
            float dz = coord[r*3+2] - coord[c*3+2];
            float rad = dx*dx + dy*dy + dz*dz;
            s[OFF_SRAD + tid] = rad;
            float inv = 1.f / (sqrtf(rad + 1e-8f) + 1.f);
            s[OFF_SCD + tid*3 + 0] = dx * inv;
            s[OFF_SCD + tid*3 + 1] = dy * inv;
            s[OFF_SCD + tid*3 + 2] = dz * inv;
        }
        __syncthreads();

        /* ---- stage edge_attr1 = edge_attr + mess ---- */
        for (int idx = tid; idx < 128*16; idx += 256) {
            int e = idx >> 4, o4 = (idx & 15) << 2;
            int eg = e0 + e;
            int mb = smb[e];
            float4 v = *(const float4*)(edge_attr + (size_t)eg*64 + o4);
            if (mb >= 0) {
                float4 m = *(const float4*)(jt_mess + (size_t)mb + o4);
                v.x += m.x; v.y += m.y; v.z += m.z; v.w += m.w;
            }
            *(float4*)(s + OFF_BUFE + e*STRIDE + o4) = v;
        }
        __syncthreads();

        u64 acc[4][4];

        /* ---- mes GEMM1: P[row]+Q[col]+rad*w1r+b1 + bufE @ w1e ; silu -> bufT */
        {
            int rn = (e0 + ty*4) >> 4;
            float4 pA = *(const float4*)(g_P + (size_t)rn*64 + c0);
            float4 pB = *(const float4*)(g_P + (size_t)rn*64 + c0 + 32);
            float pv[8] = {pA.x,pA.y,pA.z,pA.w,pB.x,pB.y,pB.z,pB.w};
            float bb[8], ww[8];
#pragma unroll
            for (int j = 0; j < 4; ++j) {
                bb[j]   = s[OFF_B1  + c0 + j];      ww[j]   = s[OFF_W1R + c0 + j];
                bb[4+j] = s[OFF_B1  + c0 + 32 + j]; ww[4+j] = s[OFF_W1R + c0 + 32 + j];
            }
#pragma unroll
            for (int i = 0; i < 4; ++i) {
                int e = ty*4 + i;
                int c = scol[e];
                float rad = s[OFF_SRAD + e];
                float4 qA = *(const float4*)(g_Q + (size_t)c*64 + c0);
                float4 qB = *(const float4*)(g_Q + (size_t)c*64 + c0 + 32);
                float qv[8] = {qA.x,qA.y,qA.z,qA.w,qB.x,qB.y,qB.z,qB.w};
                float v[8];
#pragma unroll
                for (int j = 0; j < 8; ++j) v[j] = bb[j] + rad*ww[j] + pv[j] + qv[j];
#pragma unroll
                for (int p = 0; p < 4; ++p) acc[i][p] = pk(v[2*p], v[2*p+1]);
            }
        }
        gemm_acc<64>(s + OFF_BUFE, s + OFF_W1E, ty, c0, acc);
#pragma unroll
        for (int i = 0; i < 4; ++i) {
            float* d = s + OFF_BUFT + (ty*4+i)*STRIDE;
            float a, b;
            upk(acc[i][0], a, b); d[c0+0]    = silu(a); d[c0+1]    = silu(b);
            upk(acc[i][1], a, b); d[c0+2]    = silu(a); d[c0+3]    = silu(b);
            upk(acc[i][2], a, b); d[c0+32]   = silu(a); d[c0+33]   = silu(b);
            upk(acc[i][3], a, b); d[c0+34]   = silu(a); d[c0+35]   = silu(b);
        }
        __syncthreads();

        /* ---- mes GEMM2: silu(bufT @ w2 + b2) * emask -> bufF, + global agg red */
#pragma unroll
        for (int i = 0; i < 4; ++i) {
            acc[i][0] = pk(s[OFF_B2+c0],    s[OFF_B2+c0+1]);
            acc[i][1] = pk(s[OFF_B2+c0+2],  s[OFF_B2+c0+3]);
            acc[i][2] = pk(s[OFF_B2+c0+32], s[OFF_B2+c0+33]);
            acc[i][3] = pk(s[OFF_B2+c0+34], s[OFF_B2+c0+35]);
        }
        gemm_acc<64>(s + OFF_BUFT, s + OFF_W2, ty, c0, acc);
#pragma unroll
        for (int i = 0; i < 4; ++i) {
            int e = ty*4 + i;
            float em = s[OFF_SEM + e];
            int c = scol[e];
            float* d = s + OFF_BUFF + e*STRIDE;
            float* ga = g_agg + (size_t)c*64;
            float a, b, v0, v1, v2, v3;
            upk(acc[i][0], a, b); v0 = silu(a)*em; v1 = silu(b)*em;
            upk(acc[i][1], a, b); v2 = silu(a)*em; v3 = silu(b)*em;
            d[c0+0] = v0; d[c0+1] = v1; d[c0+2] = v2; d[c0+3] = v3;
            red4(ga + c0, v0, v1, v2, v3);
            upk(acc[i][2], a, b); v0 = silu(a)*em; v1 = silu(b)*em;
            upk(acc[i][3], a, b); v2 = silu(a)*em; v3 = silu(b)*em;
            d[c0+32] = v0; d[c0+33] = v1; d[c0+34] = v2; d[c0+35] = v3;
            red4(ga + c0 + 32, v0, v1, v2, v3);
        }
        __syncthreads();

        /* ---- coord gate: silu(bufF @ cw1 + cb1) . cw2 -> sgate ---- */
#pragma unroll
        for (int i = 0; i < 4; ++i) {
            acc[i][0] = pk(s[OFF_CB1+c0],    s[OFF_CB1+c0+1]);
            acc[i][1] = pk(s[OFF_CB1+c0+2],  s[OFF_CB1+c0+3]);
            acc[i][2] = pk(s[OFF_CB1+c0+32], s[OFF_CB1+c0+33]);
            acc[i][3] = pk(s[OFF_CB1+c0+34], s[OFF_CB1+c0+35]);
        }
        gemm_acc<64>(s + OFF_BUFF, s + OFF_CW1, ty, c0, acc);
        {
            float cw[8];
#pragma unroll
            for (int j = 0; j < 4; ++j) {
                cw[j]   = s[OFF_CW2 + c0 + j];
                cw[4+j] = s[OFF_CW2 + c0 + 32 + j];
            }
#pragma unroll
            for (int i = 0; i < 4; ++i) {
                float pd = 0.f, a, b;
                upk(acc[i][0], a, b); pd += silu(a)*cw[0] + silu(b)*cw[1];
                upk(acc[i][1], a, b); pd += silu(a)*cw[2] + silu(b)*cw[3];
                upk(acc[i][2], a, b); pd += silu(a)*cw[4] + silu(b)*cw[5];
                upk(acc[i][3], a, b); pd += silu(a)*cw[6] + silu(b)*cw[7];
                pd += __shfl_xor_sync(0xffffffffu, pd, 1);
                pd += __shfl_xor_sync(0xffffffffu, pd, 2);
                pd += __shfl_xor_sync(0xffffffffu, pd, 4);
                if (tx == 0) s[OFF_SGT + ty*4 + i] = pd;
            }
        }
        __syncthreads();

        if (tid < 128) {
            float g = s[OFF_SGT + tid] * s[OFF_SEM + tid];
            s[OFF_STR + tid*3 + 0] = s[OFF_SCD + tid*3 + 0] * g;
            s[OFF_STR + tid*3 + 1] = s[OFF_SCD + tid*3 + 1] * g;
            s[OFF_STR + tid*3 + 2] = s[OFF_SCD + tid*3 + 2] * g;
        }
        __syncthreads();

        if (tid < NODES_PER_TILE*3) {
            int n = tid / 3, c = tid - n*3;
            float sum = 0.f;
#pragma unroll
            for (int k = 0; k < DEG; ++k) sum += s[OFF_STR + (n*DEG + k)*3 + c];
            int gn = tile*NODES_PER_TILE + n;
            outC[gn*3 + c] = (coord[gn*3 + c] + sum) * node_mask[gn];
        }

        /* ---- edge MLP: silu([bufF, rad, bufE] @ ew1 + eb1) -> bufT ---- */
        {
            float bb[8], ww[8];
#pragma unroll
            for (int j = 0; j < 4; ++j) {
                bb[j]   = s[OFF_EB1 + c0 + j];
                bb[4+j] = s[OFF_EB1 + c0 + 32 + j];
                ww[j]   = s[OFF_EW1 + 64*64 + c0 + j];
                ww[4+j] = s[OFF_EW1 + 64*64 + c0 + 32 + j];
            }
#pragma unroll
            for (int i = 0; i < 4; ++i) {
                float rad = s[OFF_SRAD + ty*4 + i];
#pragma unroll
                for (int p = 0; p < 4; ++p)
                    acc[i][p] = pk(bb[2*p] + rad*ww[2*p], bb[2*p+1] + rad*ww[2*p+1]);
            }
        }
        gemm_acc<64>(s + OFF_BUFF, s + OFF_EW1,         ty, c0, acc);
        gemm_acc<64>(s + OFF_BUFE, s + OFF_EW1 + 65*64, ty, c0, acc);
#pragma unroll
        for (int i = 0; i < 4; ++i) {
            float* d = s + OFF_BUFT + (ty*4+i)*STRIDE;
            float a, b;
            upk(acc[i][0], a, b); d[c0+0]  = silu(a); d[c0+1]  = silu(b);
            upk(acc[i][1], a, b); d[c0+2]  = silu(a); d[c0+3]  = silu(b);
            upk(acc[i][2], a, b); d[c0+32] = silu(a); d[c0+33] = silu(b);
            upk(acc[i][3], a, b); d[c0+34] = silu(a); d[c0+35] = silu(b);
        }
        __syncthreads();

        /* ---- edge GEMM2: (bufT @ ew2 + eb2) * emask -> outE ---- */
#pragma unroll
        for (int i = 0; i < 4; ++i) {
            acc[i][0] = pk(s[OFF_EB2+c0],    s[OFF_EB2+c0+1]);
            acc[i][1] = pk(s[OFF_EB2+c0+2],  s[OFF_EB2+c0+3]);
            acc[i][2] = pk(s[OFF_EB2+c0+32], s[OFF_EB2+c0+33]);
            acc[i][3] = pk(s[OFF_EB2+c0+34], s[OFF_EB2+c0+35]);
        }
        gemm_acc<64>(s + OFF_BUFT, s + OFF_EW2, ty, c0, acc);
#pragma unroll
        for (int i = 0; i < 4; ++i) {
            int e = ty*4 + i;
            float em = s[OFF_SEM + e];
            size_t eg = (size_t)(e0 + e);
            float a, b, v0, v1, v2, v3;
            upk(acc[i][0], a, b); v0 = a*em; v1 = b*em;
            upk(acc[i][1], a, b); v2 = a*em; v3 = b*em;
            *(float4*)(outE + eg*64 + c0) = make_float4(v0, v1, v2, v3);
            upk(acc[i][2], a, b); v0 = a*em; v1 = b*em;
            upk(acc[i][3], a, b); v2 = a*em; v3 = b*em;
            *(float4*)(outE + eg*64 + c0 + 32) = make_float4(v0, v1, v2, v3);
        }
        __syncthreads();  /* buffers reused next tile */
    }
}

/* =========================== Kernel C: node MLP ============================ */
#define C_NW1  0
#define C_NW2  8192
#define C_NB1  12288
#define C_NB2  12352
#define C_BA   12416
#define C_BB   (12416 + 128*STRIDE)
#define C_BT   (12416 + 2*128*STRIDE)
#define C_SMEM_FLOATS (12416 + 3*128*STRIDE)

__global__ void __launch_bounds__(256, 1)
kernel_nodes(const float* __restrict__ node_w1,
             const float* __restrict__ node_b1,
             const float* __restrict__ node_w2,
             const float* __restrict__ node_b2,
             const float* __restrict__ node_mask,
             float* __restrict__ outH)
{
    extern __shared__ float s[];
    const int tid = threadIdx.x;
    const int nb  = blockIdx.x * 128;
    const int tx = tid & 7, ty = tid >> 3;
    const int c0 = tx * 4;

    for (int idx = tid; idx < 8192; idx += 256) s[C_NW1 + idx] = node_w1[idx];
    for (int idx = tid; idx < 4096; idx += 256) s[C_NW2 + idx] = node_w2[idx];
    if (tid < 64) { s[C_NB1 + tid] = node_b1[tid]; s[C_NB2 + tid] = node_b2[tid]; }
    for (int idx = tid; idx < 128*16; idx += 256) {
        int l = idx >> 4, o4 = (idx & 15) << 2;
        size_t base = (size_t)(nb + l)*64 + o4;
        *(float4*)(s + C_BA + l*STRIDE + o4) = *(const float4*)(g_h1 + base);
        *(float4*)(s + C_BB + l*STRIDE + o4) = *(const float4*)(g_agg + base);
    }
    __syncthreads();

    u64 acc[4][4];
#pragma unroll
    for (int i = 0; i < 4; ++i) {
        acc[i][0] = pk(s[C_NB1+c0],    s[C_NB1+c0+1]);
        acc[i][1] = pk(s[C_NB1+c0+2],  s[C_NB1+c0+3]);
        acc[i][2] = pk(s[C_NB1+c0+32], s[C_NB1+c0+33]);
        acc[i][3] = pk(s[C_NB1+c0+34], s[C_NB1+c0+35]);
    }
    gemm_acc<64>(s + C_BA, s + C_NW1,         ty, c0, acc);
    gemm_acc<64>(s + C_BB, s + C_NW1 + 64*64, ty, c0, acc);
#pragma unroll
    for (int i = 0; i < 4; ++i) {
        float* d = s + C_BT + (ty*4+i)*STRIDE;
        float a, b;
        upk(acc[i][0], a, b); d[c0+0]  = silu(a); d[c0+1]  = silu(b);
        upk(acc[i][1], a, b); d[c0+2]  = silu(a); d[c0+3]  = silu(b);
        upk(acc[i][2], a, b); d[c0+32] = silu(a); d[c0+33] = silu(b);
        upk(acc[i][3], a, b); d[c0+34] = silu(a); d[c0+35] = silu(b);
    }
    __syncthreads();

#pragma unroll
    for (int i = 0; i < 4; ++i) {
        acc[i][0] = pk(s[C_NB2+c0],    s[C_NB2+c0+1]);
        acc[i][1] = pk(s[C_NB2+c0+2],  s[C_NB2+c0+3]);
        acc[i][2] = pk(s[C_NB2+c0+32], s[C_NB2+c0+33]);
        acc[i][3] = pk(s[C_NB2+c0+34], s[C_NB2+c0+35]);
    }
    gemm_acc<64>(s + C_BT, s + C_NW2, ty, c0, acc);
#pragma unroll
    for (int i = 0; i < 4; ++i) {
        int l = ty*4 + i;
        int node = nb + l;
        float nm = node_mask[node];
        const float* h1p = s + C_BA + l*STRIDE;
        float a, b, v0, v1, v2, v3;
        size_t base = (size_t)node*64;
        upk(acc[i][0], a, b); v0 = (h1p[c0+0] + a)*nm; v1 = (h1p[c0+1] + b)*nm;
        upk(acc[i][1], a, b); v2 = (h1p[c0+2] + a)*nm; v3 = (h1p[c0+3] + b)*nm;
        *(float4*)(outH + base + c0) = make_float4(v0, v1, v2, v3);
        upk(acc[i][2], a, b); v0 = (h1p[c0+32] + a)*nm; v1 = (h1p[c0+33] + b)*nm;
        upk(acc[i][3], a, b); v2 = (h1p[c0+34] + a)*nm; v3 = (h1p[c0+35] + b)*nm;
        *(float4*)(outH + base + c0 + 32) = make_float4(v0, v1, v2, v3);
    }
}

/* =============================== launcher ================================== */
extern "C" void kernel_launch(void* const* d_in, const int* in_sizes, int n_in,
                              void* d_out, int out_size)
{
    const float* h          = (const float*)d_in[0];
    const float* coord      = (const float*)d_in[1];
    const float* edge_attr  = (const float*)d_in[2];
    const float* jt_mess    = (const float*)d_in[3];
    const float* node_embed = (const float*)d_in[4];
    const float* node_mask  = (const float*)d_in[5];
    const float* edge_mask  = (const float*)d_in[6];
    const float* mes_w1     = (const float*)d_in[7];
    const float* mes_b1     = (const float*)d_in[8];
    const float* mes_w2     = (const float*)d_in[9];
    const float* mes_b2     = (const float*)d_in[10];
    const float* edge_w1    = (const float*)d_in[11];
    const float* edge_b1    = (const float*)d_in[12];
    const float* edge_w2    = (const float*)d_in[13];
    const float* edge_b2    = (const float*)d_in[14];
    const float* node_w1    = (const float*)d_in[15];
    const float* node_b1    = (const float*)d_in[16];
    const float* node_w2    = (const float*)d_in[17];
    const float* node_b2    = (const float*)d_in[18];
    const float* coord_w1   = (const float*)d_in[19];
    const float* coord_b1   = (const float*)d_in[20];
    const float* coord_w2   = (const float*)d_in[21];
    const int*   edge_index = (const int*)d_in[22];
    const int*   mess_holder= (const int*)d_in[23];
    const int*   node_holder= (const int*)d_in[24];
    const int*   jt_idx     = (const int*)d_in[25];

    float* outH = (float*)d_out;
    float* outC = outH + (size_t)NN*HD;
    float* outE = outC + (size_t)NN*3;

    const int smemA = A_SMEM_FLOATS * 4;
    const int smemB = B_SMEM_FLOATS * 4;
    const int smemC = C_SMEM_FLOATS * 4;

    cudaFuncSetAttribute(kernel_prep,  cudaFuncAttributeMaxDynamicSharedMemorySize, smemA);
    cudaFuncSetAttribute(kernel_edges, cudaFuncAttributeMaxDynamicSharedMemorySize, smemB);
    cudaFuncSetAttribute(kernel_nodes, cudaFuncAttributeMaxDynamicSharedMemorySize, smemC);

    kernel_prep<<<NN/128, 256, smemA>>>(h, node_embed, mes_w1, node_holder, jt_idx);

    kernel_edges<<<148, 256, smemB>>>(coord, edge_attr, jt_mess, node_mask, edge_mask,
                                      mes_w1, mes_b1, mes_w2, mes_b2,
                                      edge_w1, edge_b1, edge_w2, edge_b2,
                                      coord_w1, coord_b1, coord_w2,
                                      edge_index + NE, mess_holder, jt_idx,
                                      outC, outE);

    kernel_nodes<<<NN/128, 256, smemC>>>(node_w1, node_b1, node_w2, node_b2,
                                         node_mask, outH);
}